// round 16
// baseline (speedup 1.0000x reference)
#include <cuda_runtime.h>
#include <cuda_bf16.h>

#define SEQ   1024
#define BATCH 512
#define NT    64
#define TPB   32    // ONE warp per chain half; lane owns tags {2L, 2L+1}

// Scratch (device globals; no allocation).
__device__ float g_vec[2][BATCH][NT];  // [0]=forward F~, [1]=backward u
__device__ int   g_kt[2][BATCH];
__device__ float g_num[BATCH];
__device__ int   g_pair[BATCH];
__device__ float g_llh[BATCH];
__device__ int   g_done;

__global__ void __launch_bounds__(TPB, 1)
crf_kernel(const float* __restrict__ em,
           const void* __restrict__ tags_raw,
           const int* __restrict__ mask,
           const float* __restrict__ startT,
           const float* __restrict__ endT,
           const float* __restrict__ trans,
           float* __restrict__ out)
{
    const int bb   = blockIdx.x;
    const int b    = bb >> 1;         // batch
    const int half = bb & 1;          // 0 = forward, 1 = backward
    const int lane = threadIdx.x;     // 0..31
    const int j0   = 2 * lane;        // owned tags (adjacent)
    const int j1   = 2 * lane + 1;

    // ---- exp(transitions) bf16x2 packed over ROW PAIRS (2k, 2k+1) ----
    // fwd: coeff for tag j at row i = exp(trans[i][j]); bwd: exp(trans[j][i])
    __nv_bfloat162 hT0[NT / 2], hT1[NT / 2];
    if (half == 0) {
#pragma unroll
        for (int k = 0; k < NT / 2; ++k) {
            hT0[k] = __floats2bfloat162_rn(__expf(trans[(2 * k) * NT + j0]),
                                           __expf(trans[(2 * k + 1) * NT + j0]));
            hT1[k] = __floats2bfloat162_rn(__expf(trans[(2 * k) * NT + j1]),
                                           __expf(trans[(2 * k + 1) * NT + j1]));
        }
    } else {
#pragma unroll
        for (int k = 0; k < NT / 2; ++k) {
            hT0[k] = __floats2bfloat162_rn(__expf(trans[j0 * NT + 2 * k]),
                                           __expf(trans[j0 * NT + 2 * k + 1]));
            hT1[k] = __floats2bfloat162_rn(__expf(trans[j1 * NT + 2 * k]),
                                           __expf(trans[j1 * NT + 2 * k + 1]));
        }
    }

    // ---- sequence length (mask monotone: mask[t] = t < length) ----
    int cnt = 0;
    for (int t = lane; t < SEQ; t += 32)
        cnt += mask[t * BATCH + b];
#pragma unroll
    for (int o = 16; o > 0; o >>= 1)
        cnt += __shfl_xor_sync(0xffffffffu, cnt, o);
    const int length = cnt;

    const int m = (length - 1) >> 1;           // meeting point
    const int n = half ? (length - 1 - m) : m; // my step count

    // ---- numerator (forward block only) ----
    if (half == 0) {
        const int*       t32 = (const int*)tags_raw;
        const long long* t64 = (const long long*)tags_raw;
        bool is64 = true;
#pragma unroll
        for (int k = 0; k < 16; ++k)
            is64 = is64 && (t32[2 * k * 1031 + 1] == 0);

        float num = 0.f;
        if (is64) {
            for (int t = 1 + lane; t < length; t += 32) {
                const int pt = (int)t64[(t - 1) * BATCH + b];
                const int ct = (int)t64[t * BATCH + b];
                num += trans[pt * NT + ct] + em[(t * BATCH + b) * NT + ct];
            }
        } else {
            for (int t = 1 + lane; t < length; t += 32) {
                const int pt = t32[(t - 1) * BATCH + b];
                const int ct = t32[t * BATCH + b];
                num += trans[pt * NT + ct] + em[(t * BATCH + b) * NT + ct];
            }
        }
#pragma unroll
        for (int o = 16; o > 0; o >>= 1)
            num += __shfl_xor_sync(0xffffffffu, num, o);
        if (lane == 0) {
            const int t0 = is64 ? (int)t64[b] : t32[b];
            const int tl = is64 ? (int)t64[(length - 1) * BATCH + b]
                                : t32[(length - 1) * BATCH + b];
            g_num[b] = num + startT[t0] + em[b * NT + t0] + endT[tl];
        }
    }

    // ---- em stream: fwd ascending from row 0, bwd descending from L-1 ----
    const int row0    = half ? (length - 1) : 0;
    const int strideV = half ? -(BATCH * NT / 2) : (BATCH * NT / 2); // float2 units
    const float2* __restrict__ em2 = (const float2*)em;
    const int base2 = (row0 * BATCH + b) * (NT / 2) + lane;

    // register-resident state: my = (beta_j0, beta_j1) in bf16x2
    unsigned my;
    {
        const float2 e0 = em2[base2];
        const float b0 = half ? __expf(endT[j0] + e0.x) : __expf(startT[j0] + e0.x);
        const float b1 = half ? __expf(endT[j1] + e0.y) : __expf(startT[j1] + e0.y);
        const __nv_bfloat162 t = __floats2bfloat162_rn(b0, b1);
        my = *(const unsigned*)&t;
    }

    const float2 f2z = make_float2(0.f, 0.f);
    float2 p0 = (1 <= n) ? em2[base2 + 1 * strideV] : f2z;
    float2 p1 = (2 <= n) ? em2[base2 + 2 * strideV] : f2z;
    float2 p2 = (3 <= n) ? em2[base2 + 3 * strideV] : f2z;
    float2 p3 = (4 <= n) ? em2[base2 + 4 * strideV] : f2z;

    int ktot = 0;
    const __nv_bfloat162 hz = __floats2bfloat162_rn(0.f, 0.f);

    // One step: 32 SHFL all-to-all + 64 HFMA2; no shared memory, no bar.
#define STEP(EXLO, EXHI, RENORM) do {                                        \
        __nv_bfloat162 a00 = hz, a01 = hz, a02 = hz, a03 = hz;                \
        __nv_bfloat162 a10 = hz, a11 = hz, a12 = hz, a13 = hz;                \
        unsigned q0w = 0;                                                     \
        _Pragma("unroll")                                                     \
        for (int k = 0; k < 32; ++k) {                                        \
            const unsigned qw = __shfl_sync(0xffffffffu, my, k);              \
            if (k == 0) q0w = qw;                                             \
            const __nv_bfloat162 q = *(const __nv_bfloat162*)&qw;             \
            if      ((k & 3) == 0) { a00 = __hfma2(q, hT0[k], a00);           \
                                     a10 = __hfma2(q, hT1[k], a10); }         \
            else if ((k & 3) == 1) { a01 = __hfma2(q, hT0[k], a01);           \
                                     a11 = __hfma2(q, hT1[k], a11); }         \
            else if ((k & 3) == 2) { a02 = __hfma2(q, hT0[k], a02);           \
                                     a12 = __hfma2(q, hT1[k], a12); }         \
            else                   { a03 = __hfma2(q, hT0[k], a03);           \
                                     a13 = __hfma2(q, hT1[k], a13); }         \
        }                                                                     \
        float scale_ = 1.0f;                                                  \
        if (RENORM) {                                                         \
            const int kk = (int)((q0w >> 7) & 0xFFu) - 127;                   \
            scale_ = __int_as_float((127 - kk) << 23);                        \
            ktot += kk;                                                       \
        }                                                                     \
        const __nv_bfloat162 s0 =                                             \
            __hadd2(__hadd2(a00, a01), __hadd2(a02, a03));                    \
        const __nv_bfloat162 s1 =                                             \
            __hadd2(__hadd2(a10, a11), __hadd2(a12, a13));                    \
        const float2 f0 = __bfloat1622float2(s0);                             \
        const float2 f1 = __bfloat1622float2(s1);                             \
        const float nb0 = (f0.x + f0.y) * ((EXLO) * scale_);                  \
        const float nb1 = (f1.x + f1.y) * ((EXHI) * scale_);                  \
        const __nv_bfloat162 t_ = __floats2bfloat162_rn(nb0, nb1);            \
        my = *(const unsigned*)&t_;                                           \
    } while (0)

    int v = 1;
    for (; v + 3 <= n; v += 4) {
        const float2 q0 = (v + 4 <= n) ? em2[base2 + (v + 4) * strideV] : f2z;
        const float2 q1 = (v + 5 <= n) ? em2[base2 + (v + 5) * strideV] : f2z;
        const float2 q2 = (v + 6 <= n) ? em2[base2 + (v + 6) * strideV] : f2z;
        const float2 q3 = (v + 7 <= n) ? em2[base2 + (v + 7) * strideV] : f2z;

        const float ex0l = __expf(p0.x), ex0h = __expf(p0.y);
        const float ex1l = __expf(p1.x), ex1h = __expf(p1.y);
        const float ex2l = __expf(p2.x), ex2h = __expf(p2.y);
        const float ex3l = __expf(p3.x), ex3h = __expf(p3.y);

        STEP(ex0l, ex0h, true);
        STEP(ex1l, ex1h, false);
        STEP(ex2l, ex2h, false);
        STEP(ex3l, ex3h, false);

        p0 = q0; p1 = q1; p2 = q2; p3 = q3;
    }
    if (v     <= n) STEP(__expf(p0.x), __expf(p0.y), false);
    if (v + 1 <= n) STEP(__expf(p1.x), __expf(p1.y), false);
    if (v + 2 <= n) STEP(__expf(p2.x), __expf(p2.y), false);
#undef STEP

    // ---- publish my half ----
    {
        const __nv_bfloat162 fin = *(const __nv_bfloat162*)&my;
        const float2 ff = __bfloat1622float2(fin);
        g_vec[half][b][j0] = ff.x;
        g_vec[half][b][j1] = ff.y;
        if (lane == 0) g_kt[half][b] = ktot;
    }

    __threadfence();
    int go = 0;
    if (lane == 0)
        go = (atomicAdd(&g_pair[b], 1) == 1) ? 1 : 0;
    go = __shfl_sync(0xffffffffu, go, 0);

    if (go) {
        __threadfence();   // acquire side
        // Z = sum_j F_m(j) * u_m(j) * exp(-em_m(j))
        const int eb = (m * BATCH + b) * NT;
        const int ja = lane, jb = lane + 32;
        float s = g_vec[0][b][ja] * g_vec[1][b][ja] * __expf(-em[eb + ja])
                + g_vec[0][b][jb] * g_vec[1][b][jb] * __expf(-em[eb + jb]);
#pragma unroll
        for (int o = 16; o > 0; o >>= 1)
            s += __shfl_xor_sync(0xffffffffu, s, o);

        if (lane == 0) {
            const int kt = g_kt[0][b] + g_kt[1][b];
            const double denom = (double)kt * 0.6931471805599453
                               + (double)logf(s);
            g_llh[b] = (float)((double)g_num[b] - denom);
            g_pair[b] = 0;                 // reset for next replay
        }

        // ---- final reduction by the last combiner ----
        __threadfence();
        int last = 0;
        if (lane == 0)
            last = (atomicAdd(&g_done, 1) == BATCH - 1) ? 1 : 0;
        last = __shfl_sync(0xffffffffu, last, 0);

        if (last) {
            double acc = 0.0;
#pragma unroll
            for (int k = 0; k < BATCH / 32; ++k)       // fixed order: 16 each
                acc += (double)g_llh[lane + k * 32];
#pragma unroll
            for (int o = 16; o > 0; o >>= 1)
                acc += __shfl_xor_sync(0xffffffffu, acc, o);
            if (lane == 0) {
                out[0] = (float)acc;
                atomicExch(&g_done, 0);    // reset for next replay
            }
        }
    }
}

extern "C" void kernel_launch(void* const* d_in, const int* in_sizes, int n_in,
                              void* d_out, int out_size)
{
    const float* em     = (const float*)d_in[0];
    const void*  tags   = (const void*)d_in[1];
    const int*   mask   = (const int*)d_in[2];
    const float* startT = (const float*)d_in[3];
    const float* endT   = (const float*)d_in[4];
    const float* trans  = (const float*)d_in[5];
    float* out = (float*)d_out;

    crf_kernel<<<2 * BATCH, TPB>>>(em, tags, mask, startT, endT, trans, out);
}